// round 15
// baseline (speedup 1.0000x reference)
#include <cuda_runtime.h>
#include <cuda_fp16.h>
#include <stdint.h>
#include <math.h>

#define D_MODEL 1024
#define N_HEADS 16
#define DK 64
#define B_SZ 2
#define L_SEQ 2048
#define MAXLEN 2048
#define LOG2E 1.4426950408889634f
#define QK_SCALE_LOG2E 0.18033688011112042f   // 0.125 * log2(e)

// Scratch (allocation-free: __device__ globals). All operand tensors fp16.
__device__ __half g_q[(size_t)B_SZ * N_HEADS * L_SEQ * DK];
__device__ __half g_k[(size_t)B_SZ * N_HEADS * L_SEQ * DK];
__device__ __half g_v[(size_t)B_SZ * N_HEADS * L_SEQ * DK];
__device__ __half g_att[(size_t)B_SZ * L_SEQ * D_MODEL];
__device__ __half g_xr[(size_t)B_SZ * L_SEQ * D_MODEL];
__device__ __half g_wqkv[(size_t)3 * D_MODEL * D_MODEL];   // TRANSPOSED [3072][1024]
__device__ __half g_wproj[(size_t)D_MODEL * D_MODEL];      // TRANSPOSED [1024][1024]

// ---------------------------------------------------------------------------
// Helpers
// ---------------------------------------------------------------------------
__device__ __forceinline__ uint32_t f2h2(float hi, float lo) {
    uint32_t d;   // low half = lo, high half = hi
    asm("cvt.rn.f16x2.f32 %0, %1, %2;" : "=r"(d) : "f"(hi), "f"(lo));
    return d;
}

__device__ __forceinline__ float ex2(float x) {
    float r;
    asm("ex2.approx.f32 %0, %1;" : "=f"(r) : "f"(x));
    return r;
}

// D += A(16x16) * B(16x8), fp16 inputs, fp32 accum
__device__ __forceinline__ void mma16(float* c, const uint32_t* a, uint32_t b0, uint32_t b1) {
    asm volatile(
        "mma.sync.aligned.m16n8k16.row.col.f32.f16.f16.f32 "
        "{%0,%1,%2,%3},{%4,%5,%6,%7},{%8,%9},{%0,%1,%2,%3};"
        : "+f"(c[0]), "+f"(c[1]), "+f"(c[2]), "+f"(c[3])
        : "r"(a[0]), "r"(a[1]), "r"(a[2]), "r"(a[3]), "r"(b0), "r"(b1));
}

__device__ __forceinline__ void ldsm4(uint32_t* r, uint32_t addr) {
    asm volatile("ldmatrix.sync.aligned.m8n8.x4.shared.b16 {%0,%1,%2,%3}, [%4];"
                 : "=r"(r[0]), "=r"(r[1]), "=r"(r[2]), "=r"(r[3]) : "r"(addr));
}
__device__ __forceinline__ void ldsm4t(uint32_t* r, uint32_t addr) {
    asm volatile("ldmatrix.sync.aligned.m8n8.x4.trans.shared.b16 {%0,%1,%2,%3}, [%4];"
                 : "=r"(r[0]), "=r"(r[1]), "=r"(r[2]), "=r"(r[3]) : "r"(addr));
}

#define CP_ASYNC16(dst_u32, src_ptr) \
    asm volatile("cp.async.cg.shared.global [%0], [%1], 16;" :: "r"(dst_u32), "l"(src_ptr))
#define CP_COMMIT() asm volatile("cp.async.commit_group;")
#define CP_WAIT1()  asm volatile("cp.async.wait_group 1;")
#define CP_WAIT0()  asm volatile("cp.async.wait_group 0;")

// ---------------------------------------------------------------------------
// Pre-pass: x -> fp16 (linear)
// ---------------------------------------------------------------------------
__global__ __launch_bounds__(256) void cvt_x_kernel(const float4* __restrict__ src, int n4)
{
    uint2* dst = (uint2*)g_xr;
    int i = blockIdx.x * 256 + threadIdx.x;
    if (i < n4) {
        float4 v = src[i];
        dst[i] = make_uint2(f2h2(v.y, v.x), f2h2(v.w, v.z));
    }
}

// ---------------------------------------------------------------------------
// Transpose + convert: dst[n][k] = fp16(src[k][n]).  K = 1024 rows in src.
// ---------------------------------------------------------------------------
template <int SEL>
__global__ __launch_bounds__(256) void transpose_cvt_kernel(
    const float* __restrict__ src, int N)
{
    __shared__ float tile[32][33];
    __half* dst = (SEL == 1) ? g_wqkv : g_wproj;
    int n0 = blockIdx.x * 32, k0 = blockIdx.y * 32;
    int tx = threadIdx.x, ty = threadIdx.y;
#pragma unroll
    for (int j = 0; j < 32; j += 8)
        tile[ty + j][tx] = src[(size_t)(k0 + ty + j) * N + n0 + tx];
    __syncthreads();
#pragma unroll
    for (int j = 0; j < 32; j += 8)
        dst[(size_t)(n0 + ty + j) * 1024 + k0 + tx] = __float2half_rn(tile[tx][ty + j]);
}

// ---------------------------------------------------------------------------
// FP16 GEMM (R13-proven 2-stage): block 128x128, 8 warps (2x4), warp 64x32,
// Kblock 32 (2 k16 steps), 2-stage cp.async, ldsm A + ldsm B (W^T [n][k]).
// smem: A[2][128][40] + B[2][128][40] halves = 40 KB.
// ---------------------------------------------------------------------------
#define G_STH 5120   // 128*40 halves per stage per operand
template <int MODE>
__global__ __launch_bounds__(256, 2) void gemm_fp16(
    const float* __restrict__ bias, float* __restrict__ out, int N)
{
    extern __shared__ __align__(16) char gsm[];
    const uint32_t smem_u32 = (uint32_t)__cvta_generic_to_shared(gsm);
    const uint32_t smemA = smem_u32;                    // [2][128][40] halves
    const uint32_t smemB = smem_u32 + 2 * G_STH * 2;

    const __half* A  = (MODE == 0) ? g_xr : g_att;
    const __half* Wt = (MODE == 0) ? g_wqkv : g_wproj;  // [N][1024]

    const int tid = threadIdx.x;
    const int wid = tid >> 5;
    const int lane = tid & 31;
    const int g = lane >> 2, t = lane & 3;
    const int wm = wid >> 2, wn = wid & 3;              // 2 x 4 warp grid
    const int rowBase = blockIdx.y * 128;
    const int colBase = blockIdx.x * 128;

    const int sub = lane >> 3, lr = lane & 7;
    uint32_t aOff[4], bOff[2];
#pragma unroll
    for (int mi = 0; mi < 4; mi++)
        aOff[mi] = (uint32_t)((wm * 64 + mi * 16 + (sub & 1) * 8 + lr) * 40
                              + (sub >> 1) * 8);
#pragma unroll
    for (int nip = 0; nip < 2; nip++)
        bOff[nip] = (uint32_t)((wn * 32 + nip * 16 + (sub & 1) * 8 + lr) * 40
                               + (sub >> 1) * 8);

    float acc[4][4][4] = {};

    auto fill = [&](int s, int kb) {
#pragma unroll
        for (int it = 0; it < 2; it++) {
            int f4 = tid + 256 * it;               // 0..511
            int m = f4 >> 2, c8 = (f4 & 3) * 8;    // 8 halves = 16B
            uint32_t da = smemA + (uint32_t)(s * G_STH + m * 40 + c8) * 2;
            CP_ASYNC16(da, A + (size_t)(rowBase + m) * 1024 + kb + c8);
            uint32_t db = smemB + (uint32_t)(s * G_STH + m * 40 + c8) * 2;
            CP_ASYNC16(db, Wt + (size_t)(colBase + m) * 1024 + kb + c8);
        }
    };

    fill(0, 0);
    CP_COMMIT();

    for (int ti = 0; ti < 32; ti++) {
        if (ti + 1 < 32) { fill((ti + 1) & 1, (ti + 1) * 32); CP_COMMIT(); CP_WAIT1(); }
        else CP_WAIT0();
        __syncthreads();

        const uint32_t stA = smemA + (uint32_t)((ti & 1) * G_STH) * 2;
        const uint32_t stB = smemB + (uint32_t)((ti & 1) * G_STH) * 2;
#pragma unroll
        for (int k16 = 0; k16 < 32; k16 += 16) {
            uint32_t a[4][4];
#pragma unroll
            for (int mi = 0; mi < 4; mi++)
                ldsm4(a[mi], stA + (aOff[mi] + k16) * 2);
            uint32_t b[2][4];
#pragma unroll
            for (int nip = 0; nip < 2; nip++)
                ldsm4(b[nip], stB + (bOff[nip] + k16) * 2);
#pragma unroll
            for (int nip = 0; nip < 2; nip++) {
#pragma unroll
                for (int mi = 0; mi < 4; mi++) {
                    mma16(acc[mi][2 * nip],     a[mi], b[nip][0], b[nip][2]);
                    mma16(acc[mi][2 * nip + 1], a[mi], b[nip][1], b[nip][3]);
                }
            }
        }
        __syncthreads();
    }

    // Epilogue. c0:(g,2t) c1:(g,2t+1) c2:(g+8,2t) c3:(g+8,2t+1)
#pragma unroll
    for (int mi = 0; mi < 4; mi++) {
#pragma unroll
        for (int ni = 0; ni < 4; ni++) {
            int row0 = rowBase + wm * 64 + mi * 16 + g;
            int col = colBase + wn * 32 + ni * 8 + 2 * t;
#pragma unroll
            for (int half_ = 0; half_ < 2; half_++) {
                int r = row0 + half_ * 8;
                float v0 = acc[mi][ni][2 * half_]     + bias[col];
                float v1 = acc[mi][ni][2 * half_ + 1] + bias[col + 1];
                if (MODE == 0) {
                    int b = r >> 11, lq = r & 2047;
                    int s = col >> 10, rem = col & 1023;
                    int hh = rem >> 6, d = rem & 63;  // even
                    __half* dst = (s == 0) ? g_q : (s == 1) ? g_k : g_v;
                    size_t rb = (((size_t)(b * N_HEADS + hh)) * L_SEQ + lq) * DK + d;
                    *(uint32_t*)&dst[rb] = f2h2(v1, v0);
                } else {
                    *(float2*)&out[(size_t)r * 1024 + col] = make_float2(v0, v1);
                }
            }
        }
    }
}

// ---------------------------------------------------------------------------
// FP16 mma flash attention v9: 256 threads (8 warps), 256-q tile,
// 3-stage K/V pipeline with ONE sync per tile, single wave (256 blocks).
//  - warp = 32 q-rows (mi=2); m16n8k16; K via ldsm, V via ldsm.trans
//  - P A-frags via cvt.rn.f16x2 from S; fixed-reference softmax, MUFU ex2
// smem: 3 x (K[64][72]+V[64][72]) halves (55.3 KB) + bias[2304] f32 = 64.5 KB
// ---------------------------------------------------------------------------
#define KV_STH 4608   // 64*72 halves
__global__ __launch_bounds__(256, 2) void attn_kernel(const float* __restrict__ bias_table)
{
    extern __shared__ __align__(16) char smc[];
    float* bsm = (float*)(smc + 6 * KV_STH * 2);   // [2304]
    const uint32_t smem_u32 = (uint32_t)__cvta_generic_to_shared(smc);

    const int tid = threadIdx.x;
    const int wid = tid >> 5, lane = tid & 31;
    const int g = lane >> 2, t = lane & 3;
    const int bh = blockIdx.y, h = bh & 15;
    const int qbase = blockIdx.x * 256;
    const int r0 = wid * 32 + g;                   // 8 warps x 32 q-rows

    const __half* qg = g_q + ((size_t)bh * L_SEQ + qbase) * DK;
    const __half* kg = g_k + (size_t)bh * L_SEQ * DK;
    const __half* vg = g_v + (size_t)bh * L_SEQ * DK;

    auto fillkv = [&](int s, int kb) {
#pragma unroll
        for (int it = 0; it < 4; it++) {
            int idx = tid + 256 * it;              // 0..1023
            if (it < 2) {                          // K: 512 chunks
                int r = idx >> 3, c8 = (idx & 7) * 8;
                uint32_t dk = smem_u32 + (uint32_t)(s * KV_STH + r * 72 + c8) * 2;
                CP_ASYNC16(dk, kg + (size_t)(kb + r) * DK + c8);
            } else {                               // V: 512 chunks
                idx -= 512;
                int r = idx >> 3, c8 = (idx & 7) * 8;
                uint32_t dv = smem_u32 + (uint32_t)((3 + s) * KV_STH + r * 72 + c8) * 2;
                CP_ASYNC16(dv, vg + (size_t)(kb + r) * DK + c8);
            }
        }
    };

    fillkv(0, 0);
    CP_COMMIT();

    // bias preload (prescaled by log2e). j = k_loc - q_loc + 255 in [0,2302];
    // src = j + 1792 - qbase in [0, 4094].
    for (int j = tid; j < 2304; j += 256) {
        int src = j + 1792 - qbase;
        bsm[j] = (src <= 4094)
                   ? LOG2E * bias_table[(size_t)src * N_HEADS + h] : 0.f;
    }

    // Q A-fragments from global (half2 = one u32 load each)
    uint32_t Qf[2][4][4];
#pragma unroll
    for (int mi = 0; mi < 2; mi++) {
        const __half* q0p = qg + (size_t)(r0 + mi * 16) * DK;
        const __half* q1p = q0p + 8 * DK;
#pragma unroll
        for (int kk = 0; kk < 4; kk++) {
            int c = kk * 16 + 2 * t;
            Qf[mi][kk][0] = *(const uint32_t*)(q0p + c);
            Qf[mi][kk][1] = *(const uint32_t*)(q1p + c);
            Qf[mi][kk][2] = *(const uint32_t*)(q0p + c + 8);
            Qf[mi][kk][3] = *(const uint32_t*)(q1p + c + 8);
        }
    }

    fillkv(1, 64);
    CP_COMMIT();

    // ldsm lane offsets (halves), stride-72 rows
    const int sub = lane >> 3, lr = lane & 7;
    uint32_t kOff[4], vOff[4];
#pragma unroll
    for (int nf2 = 0; nf2 < 4; nf2++)   // K: rows = tokens, col = d (k16 base added)
        kOff[nf2] = (uint32_t)((nf2 * 16 + (sub & 1) * 8 + lr) * 72 + (sub >> 1) * 8);
#pragma unroll
    for (int df2 = 0; df2 < 4; df2++)   // V trans: rows = tokens (k16 base added), col = d
        vOff[df2] = (uint32_t)(((sub >> 1) * 8 + lr) * 72 + df2 * 16 + (sub & 1) * 8);

    float O[2][8][4];
#pragma unroll
    for (int mi = 0; mi < 2; mi++)
#pragma unroll
        for (int df = 0; df < 8; df++)
#pragma unroll
            for (int e = 0; e < 4; e++) O[mi][df][e] = 0.f;
    float l_[2][2] = {{0.f, 0.f}, {0.f, 0.f}};

    for (int ti = 0; ti < 32; ti++) {
        const int kb = ti * 64;
        if (ti < 31) CP_WAIT1(); else CP_WAIT0();   // fill ti complete
        __syncthreads();                             // + all warps done tile ti-1
        if (ti + 2 < 32) { fillkv((ti + 2) % 3, kb + 128); CP_COMMIT(); }

        const int s = ti % 3;
        const uint32_t stK = smem_u32 + (uint32_t)(s * KV_STH) * 2;
        const uint32_t stV = smem_u32 + (uint32_t)((3 + s) * KV_STH) * 2;

        // S = Q K^T : 4 k16 steps x 4 token-pair blocks
        float S[2][8][4];
#pragma unroll
        for (int mi = 0; mi < 2; mi++)
#pragma unroll
            for (int nf = 0; nf < 8; nf++)
#pragma unroll
                for (int e = 0; e < 4; e++) S[mi][nf][e] = 0.f;

#pragma unroll
        for (int kk = 0; kk < 4; kk++) {
#pragma unroll
            for (int nf2 = 0; nf2 < 4; nf2++) {
                uint32_t bK[4];   // r0=b0 tok0, r1=b0 tok1, r2=b1 tok0, r3=b1 tok1
                ldsm4(bK, stK + (kOff[nf2] + kk * 16) * 2);
                mma16(S[0][2 * nf2],     Qf[0][kk], bK[0], bK[2]);
                mma16(S[0][2 * nf2 + 1], Qf[0][kk], bK[1], bK[3]);
                mma16(S[1][2 * nf2],     Qf[1][kk], bK[0], bK[2]);
                mma16(S[1][2 * nf2 + 1], Qf[1][kk], bK[1], bK[3]);
            }
        }

        // Fixed-reference softmax (fp32), accumulate row sums
#pragma unroll
        for (int mi = 0; mi < 2; mi++) {
            int q0 = r0 + mi * 16;
            float rs0 = 0.f, rs1 = 0.f;
#pragma unroll
            for (int nf = 0; nf < 8; nf++) {
                int j0 = kb + 8 * nf + 2 * t - q0 + 255;
                S[mi][nf][0] = ex2(fmaf(S[mi][nf][0], QK_SCALE_LOG2E, bsm[j0]));
                S[mi][nf][1] = ex2(fmaf(S[mi][nf][1], QK_SCALE_LOG2E, bsm[j0 + 1]));
                S[mi][nf][2] = ex2(fmaf(S[mi][nf][2], QK_SCALE_LOG2E, bsm[j0 - 8]));
                S[mi][nf][3] = ex2(fmaf(S[mi][nf][3], QK_SCALE_LOG2E, bsm[j0 - 7]));
                rs0 += S[mi][nf][0] + S[mi][nf][1];
                rs1 += S[mi][nf][2] + S[mi][nf][3];
            }
            rs0 += __shfl_xor_sync(0xffffffffu, rs0, 1);
            rs0 += __shfl_xor_sync(0xffffffffu, rs0, 2);
            rs1 += __shfl_xor_sync(0xffffffffu, rs1, 1);
            rs1 += __shfl_xor_sync(0xffffffffu, rs1, 2);
            l_[mi][0] += rs0;
            l_[mi][1] += rs1;
        }

        // O += P @ V : P A-frags by f16x2 packing of S; V B-frags via ldsm.trans
#pragma unroll
        for (int kk = 0; kk < 4; kk++) {
            uint32_t aP[2][4];
#pragma unroll
            for (int mi = 0; mi < 2; mi++) {
                aP[mi][0] = f2h2(S[mi][2 * kk][1],     S[mi][2 * kk][0]);
                aP[mi][1] = f2h2(S[mi][2 * kk][3],     S[mi][2 * kk][2]);
                aP[mi][2] = f2h2(S[mi][2 * kk + 1][1], S[mi][2 * kk + 1][0]);
                aP[mi][3] = f2h2(S[mi][2 * kk + 1][3], S[mi][2 * kk + 1][2]);
            }
#pragma unroll
            for (int df2 = 0; df2 < 4; df2++) {
                uint32_t bV[4];
                ldsm4t(bV, stV + (vOff[df2] + kk * 16 * 72) * 2);
                mma16(O[0][2 * df2],     aP[0], bV[0], bV[2]);
                mma16(O[0][2 * df2 + 1], aP[0], bV[1], bV[3]);
                mma16(O[1][2 * df2],     aP[1], bV[0], bV[2]);
                mma16(O[1][2 * df2 + 1], aP[1], bV[1], bV[3]);
            }
        }
    }

    // Normalize + write g_att [B, L, H*dk] fp16
    int b = bh >> 4;
#pragma unroll
    for (int mi = 0; mi < 2; mi++) {
        float inv0 = 1.0f / l_[mi][0], inv1 = 1.0f / l_[mi][1];
        int q0 = qbase + r0 + mi * 16;
#pragma unroll
        for (int df = 0; df < 8; df++) {
            int d = 8 * df + 2 * t;
            size_t base0 = ((size_t)b * L_SEQ + q0) * D_MODEL + h * DK + d;
            size_t base1 = ((size_t)b * L_SEQ + q0 + 8) * D_MODEL + h * DK + d;
            *(uint32_t*)&g_att[base0] =
                f2h2(O[mi][df][1] * inv0, O[mi][df][0] * inv0);
            *(uint32_t*)&g_att[base1] =
                f2h2(O[mi][df][3] * inv1, O[mi][df][2] * inv1);
        }
    }
}

// ---------------------------------------------------------------------------
extern "C" void kernel_launch(void* const* d_in, const int* in_sizes, int n_in,
                              void* d_out, int out_size) {
    const float* x          = (const float*)d_in[0];
    const float* qkv_w      = (const float*)d_in[1];
    const float* qkv_b      = (const float*)d_in[2];
    const float* proj_w     = (const float*)d_in[3];
    const float* proj_b     = (const float*)d_in[4];
    const float* bias_table = (const float*)d_in[5];
    float* out = (float*)d_out;

    size_t gemm_smem = (size_t)(4 * G_STH) * 2;             // 40960 B
    size_t attn_smem = (size_t)(6 * KV_STH) * 2 + 2304 * 4; // 64512 B

    static int attrs_set = 0;
    if (!attrs_set) {
        cudaFuncSetAttribute(gemm_fp16<0>,
                             cudaFuncAttributeMaxDynamicSharedMemorySize, (int)gemm_smem);
        cudaFuncSetAttribute(gemm_fp16<1>,
                             cudaFuncAttributeMaxDynamicSharedMemorySize, (int)gemm_smem);
        cudaFuncSetAttribute(attn_kernel,
                             cudaFuncAttributeMaxDynamicSharedMemorySize, (int)attn_smem);
        attrs_set = 1;
    }

    // Pre-pass: x -> fp16; weights transpose+convert to fp16 [n][k]
    cvt_x_kernel<<<4096, 256>>>((const float4*)x, 1048576);
    transpose_cvt_kernel<1><<<dim3(96, 32), dim3(32, 8)>>>(qkv_w, 3072);
    transpose_cvt_kernel<2><<<dim3(32, 32), dim3(32, 8)>>>(proj_w, 1024);

    // QKV projection: M=4096, N=3072
    gemm_fp16<0><<<dim3(24, 32), 256, gemm_smem>>>(qkv_b, nullptr, 3072);

    // Attention: 8 q-tiles x (B*H=32) = 256 blocks (single wave)
    attn_kernel<<<dim3(L_SEQ / 256, B_SZ * N_HEADS), 256, attn_smem>>>(bias_table);

    // Output projection: M=4096, N=1024
    gemm_fp16<1><<<dim3(8, 32), 256, gemm_smem>>>(proj_b, out, 1024);
}

// round 16
// speedup vs baseline: 1.3474x; 1.3474x over previous
#include <cuda_runtime.h>
#include <cuda_fp16.h>
#include <stdint.h>
#include <math.h>

#define D_MODEL 1024
#define N_HEADS 16
#define DK 64
#define B_SZ 2
#define L_SEQ 2048
#define MAXLEN 2048
#define LOG2E 1.4426950408889634f
#define QK_SCALE_LOG2E 0.18033688011112042f   // 0.125 * log2(e)

// Scratch (allocation-free: __device__ globals). All operand tensors fp16.
__device__ __half g_q[(size_t)B_SZ * N_HEADS * L_SEQ * DK];
__device__ __half g_k[(size_t)B_SZ * N_HEADS * L_SEQ * DK];
__device__ __half g_v[(size_t)B_SZ * N_HEADS * L_SEQ * DK];
__device__ __half g_att[(size_t)B_SZ * L_SEQ * D_MODEL];
__device__ __half g_xr[(size_t)B_SZ * L_SEQ * D_MODEL];
__device__ __half g_wqkv[(size_t)3 * D_MODEL * D_MODEL];   // TRANSPOSED [3072][1024]
__device__ __half g_wproj[(size_t)D_MODEL * D_MODEL];      // TRANSPOSED [1024][1024]

// ---------------------------------------------------------------------------
// Helpers
// ---------------------------------------------------------------------------
__device__ __forceinline__ uint32_t f2h2(float hi, float lo) {
    uint32_t d;   // low half = lo, high half = hi
    asm("cvt.rn.f16x2.f32 %0, %1, %2;" : "=r"(d) : "f"(hi), "f"(lo));
    return d;
}

__device__ __forceinline__ float ex2(float x) {
    float r;
    asm("ex2.approx.f32 %0, %1;" : "=f"(r) : "f"(x));
    return r;
}

// D += A(16x16) * B(16x8), fp16 inputs, fp32 accum
__device__ __forceinline__ void mma16(float* c, const uint32_t* a, uint32_t b0, uint32_t b1) {
    asm volatile(
        "mma.sync.aligned.m16n8k16.row.col.f32.f16.f16.f32 "
        "{%0,%1,%2,%3},{%4,%5,%6,%7},{%8,%9},{%0,%1,%2,%3};"
        : "+f"(c[0]), "+f"(c[1]), "+f"(c[2]), "+f"(c[3])
        : "r"(a[0]), "r"(a[1]), "r"(a[2]), "r"(a[3]), "r"(b0), "r"(b1));
}

__device__ __forceinline__ void ldsm4(uint32_t* r, uint32_t addr) {
    asm volatile("ldmatrix.sync.aligned.m8n8.x4.shared.b16 {%0,%1,%2,%3}, [%4];"
                 : "=r"(r[0]), "=r"(r[1]), "=r"(r[2]), "=r"(r[3]) : "r"(addr));
}
__device__ __forceinline__ void ldsm4t(uint32_t* r, uint32_t addr) {
    asm volatile("ldmatrix.sync.aligned.m8n8.x4.trans.shared.b16 {%0,%1,%2,%3}, [%4];"
                 : "=r"(r[0]), "=r"(r[1]), "=r"(r[2]), "=r"(r[3]) : "r"(addr));
}

#define CP_ASYNC16(dst_u32, src_ptr) \
    asm volatile("cp.async.cg.shared.global [%0], [%1], 16;" :: "r"(dst_u32), "l"(src_ptr))
#define CP_COMMIT() asm volatile("cp.async.commit_group;")
#define CP_WAIT1()  asm volatile("cp.async.wait_group 1;")
#define CP_WAIT0()  asm volatile("cp.async.wait_group 0;")

// ---------------------------------------------------------------------------
// Pre-pass: x -> fp16 (linear)
// ---------------------------------------------------------------------------
__global__ __launch_bounds__(256) void cvt_x_kernel(const float4* __restrict__ src, int n4)
{
    uint2* dst = (uint2*)g_xr;
    int i = blockIdx.x * 256 + threadIdx.x;
    if (i < n4) {
        float4 v = src[i];
        dst[i] = make_uint2(f2h2(v.y, v.x), f2h2(v.w, v.z));
    }
}

// ---------------------------------------------------------------------------
// Transpose + convert: dst[n][k] = fp16(src[k][n]).  K = 1024 rows in src.
// ---------------------------------------------------------------------------
template <int SEL>
__global__ __launch_bounds__(256) void transpose_cvt_kernel(
    const float* __restrict__ src, int N)
{
    __shared__ float tile[32][33];
    __half* dst = (SEL == 1) ? g_wqkv : g_wproj;
    int n0 = blockIdx.x * 32, k0 = blockIdx.y * 32;
    int tx = threadIdx.x, ty = threadIdx.y;
#pragma unroll
    for (int j = 0; j < 32; j += 8)
        tile[ty + j][tx] = src[(size_t)(k0 + ty + j) * N + n0 + tx];
    __syncthreads();
#pragma unroll
    for (int j = 0; j < 32; j += 8)
        dst[(size_t)(n0 + ty + j) * 1024 + k0 + tx] = __float2half_rn(tile[tx][ty + j]);
}

// ---------------------------------------------------------------------------
// FP16 GEMM v2: block 128x128, 8 warps (2x4), warp 64x32, Kblock 64
// (4 k16 steps -> 16 iterations, half the barriers), 2-stage cp.async,
// ldsm A + ldsm B (W^T [n][k]).
// smem: 2 stages x (A[128][72]+B[128][72]) halves = 73.7 KB -> 2 CTA/SM.
// ---------------------------------------------------------------------------
#define G_STH 9216   // 128*72 halves per stage per operand
template <int MODE>
__global__ __launch_bounds__(256, 2) void gemm_fp16(
    const float* __restrict__ bias, float* __restrict__ out, int N)
{
    extern __shared__ __align__(16) char gsm[];
    const uint32_t smem_u32 = (uint32_t)__cvta_generic_to_shared(gsm);
    const uint32_t smemA = smem_u32;                    // [2][128][72] halves
    const uint32_t smemB = smem_u32 + 2 * G_STH * 2;

    const __half* A  = (MODE == 0) ? g_xr : g_att;
    const __half* Wt = (MODE == 0) ? g_wqkv : g_wproj;  // [N][1024]

    const int tid = threadIdx.x;
    const int wid = tid >> 5;
    const int lane = tid & 31;
    const int g = lane >> 2, t = lane & 3;
    const int wm = wid >> 2, wn = wid & 3;              // 2 x 4 warp grid
    const int rowBase = blockIdx.y * 128;
    const int colBase = blockIdx.x * 128;

    const int sub = lane >> 3, lr = lane & 7;
    uint32_t aOff[4], bOff[2];
#pragma unroll
    for (int mi = 0; mi < 4; mi++)
        aOff[mi] = (uint32_t)((wm * 64 + mi * 16 + (sub & 1) * 8 + lr) * 72
                              + (sub >> 1) * 8);
#pragma unroll
    for (int nip = 0; nip < 2; nip++)
        bOff[nip] = (uint32_t)((wn * 32 + nip * 16 + (sub & 1) * 8 + lr) * 72
                               + (sub >> 1) * 8);

    float acc[4][4][4] = {};

    auto fill = [&](int s, int kb) {
#pragma unroll
        for (int it = 0; it < 8; it++) {
            int idx = tid + 256 * it;              // 0..2047
            if (it < 4) {                          // A: 1024 chunks
                int m = idx >> 3, c8 = (idx & 7) * 8;
                uint32_t da = smemA + (uint32_t)(s * G_STH + m * 72 + c8) * 2;
                CP_ASYNC16(da, A + (size_t)(rowBase + m) * 1024 + kb + c8);
            } else {                               // B: 1024 chunks
                idx -= 1024;
                int m = idx >> 3, c8 = (idx & 7) * 8;
                uint32_t db = smemB + (uint32_t)(s * G_STH + m * 72 + c8) * 2;
                CP_ASYNC16(db, Wt + (size_t)(colBase + m) * 1024 + kb + c8);
            }
        }
    };

    fill(0, 0);
    CP_COMMIT();

    for (int ti = 0; ti < 16; ti++) {
        if (ti + 1 < 16) { fill((ti + 1) & 1, (ti + 1) * 64); CP_COMMIT(); CP_WAIT1(); }
        else CP_WAIT0();
        __syncthreads();

        const uint32_t stA = smemA + (uint32_t)((ti & 1) * G_STH) * 2;
        const uint32_t stB = smemB + (uint32_t)((ti & 1) * G_STH) * 2;
#pragma unroll
        for (int k16 = 0; k16 < 64; k16 += 16) {
            uint32_t a[4][4];
#pragma unroll
            for (int mi = 0; mi < 4; mi++)
                ldsm4(a[mi], stA + (aOff[mi] + k16) * 2);
            uint32_t b[2][4];
#pragma unroll
            for (int nip = 0; nip < 2; nip++)
                ldsm4(b[nip], stB + (bOff[nip] + k16) * 2);
#pragma unroll
            for (int nip = 0; nip < 2; nip++) {
#pragma unroll
                for (int mi = 0; mi < 4; mi++) {
                    mma16(acc[mi][2 * nip],     a[mi], b[nip][0], b[nip][2]);
                    mma16(acc[mi][2 * nip + 1], a[mi], b[nip][1], b[nip][3]);
                }
            }
        }
        __syncthreads();
    }

    // Epilogue. c0:(g,2t) c1:(g,2t+1) c2:(g+8,2t) c3:(g+8,2t+1)
#pragma unroll
    for (int mi = 0; mi < 4; mi++) {
#pragma unroll
        for (int ni = 0; ni < 4; ni++) {
            int row0 = rowBase + wm * 64 + mi * 16 + g;
            int col = colBase + wn * 32 + ni * 8 + 2 * t;
#pragma unroll
            for (int half_ = 0; half_ < 2; half_++) {
                int r = row0 + half_ * 8;
                float v0 = acc[mi][ni][2 * half_]     + bias[col];
                float v1 = acc[mi][ni][2 * half_ + 1] + bias[col + 1];
                if (MODE == 0) {
                    int b = r >> 11, lq = r & 2047;
                    int s = col >> 10, rem = col & 1023;
                    int hh = rem >> 6, d = rem & 63;  // even
                    __half* dst = (s == 0) ? g_q : (s == 1) ? g_k : g_v;
                    size_t rb = (((size_t)(b * N_HEADS + hh)) * L_SEQ + lq) * DK + d;
                    *(uint32_t*)&dst[rb] = f2h2(v1, v0);
                } else {
                    *(float2*)&out[(size_t)r * 1024 + col] = make_float2(v0, v1);
                }
            }
        }
    }
}

// ---------------------------------------------------------------------------
// FP16 mma flash attention (R14-proven): 128 threads (4 warps), 128-q tile,
// 3-stage K/V pipeline, ONE sync per tile.
//  - warp = 32 q-rows (mi=2); m16n8k16; K via ldsm, V via ldsm.trans
//  - P A-frags via cvt.rn.f16x2 from S; fixed-reference softmax, MUFU ex2
// smem: 3 x (K[64][72]+V[64][72]) halves (55.3 KB) + bias[2176] f32 = 64 KB
// ---------------------------------------------------------------------------
#define KV_STH 4608   // 64*72 halves
__global__ __launch_bounds__(128, 2) void attn_kernel(const float* __restrict__ bias_table)
{
    extern __shared__ __align__(16) char smc[];
    float* bsm = (float*)(smc + 6 * KV_STH * 2);   // [2176]
    const uint32_t smem_u32 = (uint32_t)__cvta_generic_to_shared(smc);

    const int tid = threadIdx.x;
    const int wid = tid >> 5, lane = tid & 31;
    const int g = lane >> 2, t = lane & 3;
    const int bh = blockIdx.y, h = bh & 15;
    const int qbase = blockIdx.x * 128;
    const int r0 = wid * 32 + g;

    const __half* qg = g_q + ((size_t)bh * L_SEQ + qbase) * DK;
    const __half* kg = g_k + (size_t)bh * L_SEQ * DK;
    const __half* vg = g_v + (size_t)bh * L_SEQ * DK;

    auto fillkv = [&](int s, int kb) {
#pragma unroll
        for (int it = 0; it < 8; it++) {
            int idx = tid + 128 * it;              // 0..1023
            int r = idx >> 3, c8 = (idx & 7) * 8;  // row 64 halves = 8 chunks
            if (it < 4) {
                uint32_t dk = smem_u32 + (uint32_t)(s * KV_STH + r * 72 + c8) * 2;
                CP_ASYNC16(dk, kg + (size_t)(kb + r) * DK + c8);
            } else {
                r -= 64;
                uint32_t dv = smem_u32 + (uint32_t)((3 + s) * KV_STH + r * 72 + c8) * 2;
                CP_ASYNC16(dv, vg + (size_t)(kb + r) * DK + c8);
            }
        }
    };

    fillkv(0, 0);
    CP_COMMIT();

    // bias preload (prescaled by log2e). src = j + 1920 - qbase in [0, 4094].
    for (int j = tid; j < 2176; j += 128)
        bsm[j] = LOG2E * bias_table[(size_t)(j + 1920 - qbase) * N_HEADS + h];

    // Q A-fragments from global (half2 = one u32 load each)
    uint32_t Qf[2][4][4];
#pragma unroll
    for (int mi = 0; mi < 2; mi++) {
        const __half* q0p = qg + (size_t)(r0 + mi * 16) * DK;
        const __half* q1p = q0p + 8 * DK;
#pragma unroll
        for (int kk = 0; kk < 4; kk++) {
            int c = kk * 16 + 2 * t;
            Qf[mi][kk][0] = *(const uint32_t*)(q0p + c);
            Qf[mi][kk][1] = *(const uint32_t*)(q1p + c);
            Qf[mi][kk][2] = *(const uint32_t*)(q0p + c + 8);
            Qf[mi][kk][3] = *(const uint32_t*)(q1p + c + 8);
        }
    }

    fillkv(1, 64);
    CP_COMMIT();

    // ldsm lane offsets (halves), stride-72 rows
    const int sub = lane >> 3, lr = lane & 7;
    uint32_t kOff[4], vOff[4];
#pragma unroll
    for (int nf2 = 0; nf2 < 4; nf2++)   // K: rows = tokens, col = d (k16 base added)
        kOff[nf2] = (uint32_t)((nf2 * 16 + (sub & 1) * 8 + lr) * 72 + (sub >> 1) * 8);
#pragma unroll
    for (int df2 = 0; df2 < 4; df2++)   // V trans: rows = tokens (k16 base added), col = d
        vOff[df2] = (uint32_t)(((sub >> 1) * 8 + lr) * 72 + df2 * 16 + (sub & 1) * 8);

    float O[2][8][4];
#pragma unroll
    for (int mi = 0; mi < 2; mi++)
#pragma unroll
        for (int df = 0; df < 8; df++)
#pragma unroll
            for (int e = 0; e < 4; e++) O[mi][df][e] = 0.f;
    float l_[2][2] = {{0.f, 0.f}, {0.f, 0.f}};

    for (int ti = 0; ti < 32; ti++) {
        const int kb = ti * 64;
        if (ti < 31) CP_WAIT1(); else CP_WAIT0();   // fill ti complete
        __syncthreads();                             // + all warps done tile ti-1
        if (ti + 2 < 32) { fillkv((ti + 2) % 3, kb + 128); CP_COMMIT(); }

        const int s = ti % 3;
        const uint32_t stK = smem_u32 + (uint32_t)(s * KV_STH) * 2;
        const uint32_t stV = smem_u32 + (uint32_t)((3 + s) * KV_STH) * 2;

        // S = Q K^T : 4 k16 steps x 4 token-pair blocks
        float S[2][8][4];
#pragma unroll
        for (int mi = 0; mi < 2; mi++)
#pragma unroll
            for (int nf = 0; nf < 8; nf++)
#pragma unroll
                for (int e = 0; e < 4; e++) S[mi][nf][e] = 0.f;

#pragma unroll
        for (int kk = 0; kk < 4; kk++) {
#pragma unroll
            for (int nf2 = 0; nf2 < 4; nf2++) {
                uint32_t bK[4];   // r0=b0 tok0, r1=b0 tok1, r2=b1 tok0, r3=b1 tok1
                ldsm4(bK, stK + (kOff[nf2] + kk * 16) * 2);
                mma16(S[0][2 * nf2],     Qf[0][kk], bK[0], bK[2]);
                mma16(S[0][2 * nf2 + 1], Qf[0][kk], bK[1], bK[3]);
                mma16(S[1][2 * nf2],     Qf[1][kk], bK[0], bK[2]);
                mma16(S[1][2 * nf2 + 1], Qf[1][kk], bK[1], bK[3]);
            }
        }

        // Fixed-reference softmax (fp32), accumulate row sums
#pragma unroll
        for (int mi = 0; mi < 2; mi++) {
            int q0 = r0 + mi * 16;
            float rs0 = 0.f, rs1 = 0.f;
#pragma unroll
            for (int nf = 0; nf < 8; nf++) {
                int j0 = kb + 8 * nf + 2 * t - q0 + 127;
                S[mi][nf][0] = ex2(fmaf(S[mi][nf][0], QK_SCALE_LOG2E, bsm[j0]));
                S[mi][nf][1] = ex2(fmaf(S[mi][nf][1], QK_SCALE_LOG2E, bsm[j0 + 1]));
                S[mi][nf][2] = ex2(fmaf(S[mi][nf][2], QK_SCALE_LOG2E, bsm[j0 - 8]));
                S[mi][nf][3] = ex2(fmaf(S[mi][nf][3], QK_SCALE_LOG2E, bsm[j0 - 7]));
                rs0 += S[mi][nf][0] + S[mi][nf][1];
                rs1 += S[mi][nf][2] + S[mi][nf][3];
            }
            rs0 += __shfl_xor_sync(0xffffffffu, rs0, 1);
            rs0 += __shfl_xor_sync(0xffffffffu, rs0, 2);
            rs1 += __shfl_xor_sync(0xffffffffu, rs1, 1);
            rs1 += __shfl_xor_sync(0xffffffffu, rs1, 2);
            l_[mi][0] += rs0;
            l_[mi][1] += rs1;
        }

        // O += P @ V : P A-frags by f16x2 packing of S; V B-frags via ldsm.trans
#pragma unroll
        for (int kk = 0; kk < 4; kk++) {
            uint32_t aP[2][4];
#pragma unroll
            for (int mi = 0; mi < 2; mi++) {
                aP[mi][0] = f2h2(S[mi][2 * kk][1],     S[mi][2 * kk][0]);
                aP[mi][1] = f2h2(S[mi][2 * kk][3],     S[mi][2 * kk][2]);
                aP[mi][2] = f2h2(S[mi][2 * kk + 1][1], S[mi][2 * kk + 1][0]);
                aP[mi][3] = f2h2(S[mi][2 * kk + 1][3], S[mi][2 * kk + 1][2]);
            }
#pragma unroll
            for (int df2 = 0; df2 < 4; df2++) {
                uint32_t bV[4];
                ldsm4t(bV, stV + (vOff[df2] + kk * 16 * 72) * 2);
                mma16(O[0][2 * df2],     aP[0], bV[0], bV[2]);
                mma16(O[0][2 * df2 + 1], aP[0], bV[1], bV[3]);
                mma16(O[1][2 * df2],     aP[1], bV[0], bV[2]);
                mma16(O[1][2 * df2 + 1], aP[1], bV[1], bV[3]);
            }
        }
    }

    // Normalize + write g_att [B, L, H*dk] fp16
    int b = bh >> 4;
#pragma unroll
    for (int mi = 0; mi < 2; mi++) {
        float inv0 = 1.0f / l_[mi][0], inv1 = 1.0f / l_[mi][1];
        int q0 = qbase + r0 + mi * 16;
#pragma unroll
        for (int df = 0; df < 8; df++) {
            int d = 8 * df + 2 * t;
            size_t base0 = ((size_t)b * L_SEQ + q0) * D_MODEL + h * DK + d;
            size_t base1 = ((size_t)b * L_SEQ + q0 + 8) * D_MODEL + h * DK + d;
            *(uint32_t*)&g_att[base0] =
                f2h2(O[mi][df][1] * inv0, O[mi][df][0] * inv0);
            *(uint32_t*)&g_att[base1] =
                f2h2(O[mi][df][3] * inv1, O[mi][df][2] * inv1);
        }
    }
}

// ---------------------------------------------------------------------------
extern "C" void kernel_launch(void* const* d_in, const int* in_sizes, int n_in,
                              void* d_out, int out_size) {
    const float* x          = (const float*)d_in[0];
    const float* qkv_w      = (const float*)d_in[1];
    const float* qkv_b      = (const float*)d_in[2];
    const float* proj_w     = (const float*)d_in[3];
    const float* proj_b     = (const float*)d_in[4];
    const float* bias_table = (const float*)d_in[5];
    float* out = (float*)d_out;

    size_t gemm_smem = (size_t)(4 * G_STH) * 2;             // 73728 B
    size_t attn_smem = (size_t)(6 * KV_STH) * 2 + 2176 * 4; // 64000 B

    static int attrs_set = 0;
    if (!attrs_set) {
        cudaFuncSetAttribute(gemm_fp16<0>,
                             cudaFuncAttributeMaxDynamicSharedMemorySize, (int)gemm_smem);
        cudaFuncSetAttribute(gemm_fp16<1>,
                             cudaFuncAttributeMaxDynamicSharedMemorySize, (int)gemm_smem);
        cudaFuncSetAttribute(attn_kernel,
                             cudaFuncAttributeMaxDynamicSharedMemorySize, (int)attn_smem);
        attrs_set = 1;
    }

    // Pre-pass: x -> fp16; weights transpose+convert to fp16 [n][k]
    cvt_x_kernel<<<4096, 256>>>((const float4*)x, 1048576);
    transpose_cvt_kernel<1><<<dim3(96, 32), dim3(32, 8)>>>(qkv_w, 3072);
    transpose_cvt_kernel<2><<<dim3(32, 32), dim3(32, 8)>>>(proj_w, 1024);

    // QKV projection: M=4096, N=3072
    gemm_fp16<0><<<dim3(24, 32), 256, gemm_smem>>>(qkv_b, nullptr, 3072);

    // Attention: 16 q-tiles x (B*H=32)
    attn_kernel<<<dim3(L_SEQ / 128, B_SZ * N_HEADS), 128, attn_smem>>>(bias_table);

    // Output projection: M=4096, N=1024
    gemm_fp16<1><<<dim3(8, 32), 256, gemm_smem>>>(proj_b, out, 1024);
}